// round 13
// baseline (speedup 1.0000x reference)
#include <cuda_runtime.h>
#include <math.h>

// Shapes (fixed by the problem)
#define B 32
#define C 256
#define H 64
#define W 64
#define HW (H*W)            // 4096
#define PLANES (B*C)        // 8192
#define RH 3                // int(0.05*64)
#define RW 6                // int(0.1*64)
#define CLAMP_SX 61.0f      // h - rh
#define CLAMP_SY 58.0f      // w - rw

#define QUARTERS 4          // fc2/final split factor for k_mlp

// PDL primitives (sm_90+)
#define GRID_DEP_LAUNCH() asm volatile("griddepcontrol.launch_dependents;" ::: "memory")
#define GRID_DEP_WAIT()   asm volatile("griddepcontrol.wait;" ::: "memory")

// Scratch (no cudaMalloc allowed)
__device__ float g_mean[PLANES];
__device__ float g_scale[PLANES];
__device__ int   g_sx[PLANES];
__device__ int   g_sy[PLANES];

// ---------------------------------------------------------------------------
// Kernel 1: per-(b,c) mean of x. Signals dependents only AFTER its loads are
// issued, so k_mlp spins up under the drain, not the streaming phase.
// ---------------------------------------------------------------------------
__global__ void __launch_bounds__(256) k_mean(const float* __restrict__ x) {
    int plane = blockIdx.x;
    const float4* xp = reinterpret_cast<const float4*>(x) + (size_t)plane * (HW / 4);
    int tid = threadIdx.x;

    float4 v0 = xp[tid];
    float4 v1 = xp[tid + 256];
    float4 v2 = xp[tid + 512];
    float4 v3 = xp[tid + 768];

    GRID_DEP_LAUNCH();   // loads issued; only reduction left

    float s = (v0.x + v0.y) + (v0.z + v0.w);
    s += (v1.x + v1.y) + (v1.z + v1.w);
    s += (v2.x + v2.y) + (v2.z + v2.w);
    s += (v3.x + v3.y) + (v3.z + v3.w);
#pragma unroll
    for (int o = 16; o; o >>= 1) s += __shfl_xor_sync(0xffffffffu, s, o);

    __shared__ float ws[8];
    if ((tid & 31) == 0) ws[tid >> 5] = s;
    __syncthreads();
    if (tid == 0) {
        float t = 0.f;
#pragma unroll
        for (int i = 0; i < 8; i++) t += ws[i];
        g_mean[plane] = t * (1.0f / (float)HW);
    }
}

// ---------------------------------------------------------------------------
// Kernel 2: MLP math. grid = (B, 2, QUARTERS). PDL consumer AND producer:
// signals its dependents (k_apply) at the top, so apply's blocks launch and
// front-load x during the mlp window (SMs/DRAM nearly idle then).
// No prefetch (suspected net-negative in R12).
// ---------------------------------------------------------------------------
__device__ __forceinline__ float sigmoidf_acc(float v) {
    return 1.0f / (1.0f + expf(-v));
}

__device__ __forceinline__ float warp_red(float s) {
#pragma unroll
    for (int o = 16; o; o >>= 1) s += __shfl_xor_sync(0xffffffffu, s, o);
    return s;
}

__global__ void __launch_bounds__(512) k_mlp(
    const float* __restrict__ se_w1,   // (16,256)
    const float* __restrict__ se_w2,   // (256,16)
    const float* __restrict__ ch_w, const float* __restrict__ ch_b,
    const float* __restrict__ cw_w, const float* __restrict__ cw_b,
    const float* __restrict__ dh_fc1w, const float* __restrict__ dh_fc1b,
    const float* __restrict__ dh_fc2w, const float* __restrict__ dh_fc2b,
    const float* __restrict__ dw_fc1w, const float* __restrict__ dw_fc1b,
    const float* __restrict__ dw_fc2w, const float* __restrict__ dw_fc2b)
{
    __shared__ float y[256];
    __shared__ float t1[16];
    __shared__ float gv[256];
    __shared__ float vh[256];
    __shared__ float th1[64];
    __shared__ float th2[256];    // this block's quarter of fc2 outputs

    int b    = blockIdx.x;
    int br   = blockIdx.y;
    int q    = blockIdx.z;        // fc2 quarter 0..3
    int tid  = threadIdx.x;
    int wid  = tid >> 5;          // 0..15
    int lane = tid & 31;

    const float* cw   = br ? cw_w    : ch_w;
    const float* cb   = br ? cw_b    : ch_b;
    const float* fc1w = br ? dw_fc1w : dh_fc1w;
    const float* fc1b = br ? dw_fc1b : dh_fc1b;
    const float* fc2w = br ? dw_fc2w : dh_fc2w;
    const float* fc2b = br ? dw_fc2b : dh_fc2b;
    int* outArr = br ? g_sy : g_sx;
    float clampv = br ? CLAMP_SY : CLAMP_SX;

    // Let k_apply launch now: its blocks front-load x during the mlp window.
    GRID_DEP_LAUNCH();

    GRID_DEP_WAIT();   // g_mean now visible

    if (tid < 256) y[tid] = g_mean[b * 256 + tid];
    __syncthreads();

    float yreg[8];
#pragma unroll
    for (int k = 0; k < 8; k++) yreg[k] = y[lane + k * 32];

    // SE squeeze: 1 output per warp
    {
        const float* r = se_w1 + wid * 256;
        float s = 0.f;
#pragma unroll
        for (int k = 0; k < 8; k++) s = fmaf(yreg[k], r[lane + k * 32], s);
        s = warp_red(s);
        if (lane == 0) t1[wid] = fmaxf(s, 0.f);
    }
    __syncthreads();

    // SE excite
    if (tid < 256) {
        const float4* r = reinterpret_cast<const float4*>(se_w2 + tid * 16);
        const float4* t = reinterpret_cast<const float4*>(t1);
        float s = 0.f;
#pragma unroll
        for (int j = 0; j < 4; j++) {
            float4 wv = r[j];
            float4 tv = t[j];
            s = fmaf(wv.x, tv.x, fmaf(wv.y, tv.y, fmaf(wv.z, tv.z, fmaf(wv.w, tv.w, s))));
        }
        float sg = sigmoidf_acc(s);
        if (br == 0 && q == 0) g_scale[b * 256 + tid] = sg;
        gv[tid] = y[tid] * sg;
    }
    __syncthreads();

    float greg[8];
#pragma unroll
    for (int k = 0; k < 8; k++) greg[k] = gv[lane + k * 32];

    // vh[256] = gv @ cw^T + cb : 16 outputs per warp
#pragma unroll 8
    for (int i = 0; i < 16; i++) {
        int o = wid * 16 + i;
        const float* r = cw + o * 256;
        float s = 0.f;
#pragma unroll
        for (int k = 0; k < 8; k++) s = fmaf(greg[k], r[lane + k * 32], s);
        s = warp_red(s);
        if (lane == 0) vh[o] = s + cb[o];
    }
    __syncthreads();

    float vreg[8];
#pragma unroll
    for (int k = 0; k < 8; k++) vreg[k] = vh[lane + k * 32];

    // th1[64] = relu(vh @ fc1w^T + fc1b) : 4 outputs per warp
#pragma unroll
    for (int i = 0; i < 4; i++) {
        int o = wid * 4 + i;
        const float* r = fc1w + o * 256;
        float s = 0.f;
#pragma unroll
        for (int k = 0; k < 8; k++) s = fmaf(vreg[k], r[lane + k * 32], s);
        s = warp_red(s);
        if (lane == 0) th1[o] = fmaxf(s + fc1b[o], 0.f);
    }
    __syncthreads();

    float t1a = th1[lane * 2];
    float t1b = th1[lane * 2 + 1];

    // th2 quarter: outputs m in [q*256, q*256+256), 16 per warp
#pragma unroll 8
    for (int i = 0; i < 16; i++) {
        int m = q * 256 + wid * 16 + i;
        float2 wv = reinterpret_cast<const float2*>(fc2w + m * 64)[lane];
        float s = fmaf(t1a, wv.x, t1b * wv.y);
        s = warp_red(s);
        if (lane == 0) th2[wid * 16 + i] = s + fc2b[m];
    }
    __syncthreads();

    // dyrelu + sigmoid + ceil/clamp for this quarter's 64 channels
    if (tid < 64) {
        int c = q * 64 + tid;            // global channel
        float v = vh[c];
        float u0 = 2.0f * sigmoidf_acc(th2[tid * 4 + 0]) - 1.0f;
        float u1 = 2.0f * sigmoidf_acc(th2[tid * 4 + 1]) - 1.0f;
        float u2 = 2.0f * sigmoidf_acc(th2[tid * 4 + 2]) - 1.0f;
        float u3 = 2.0f * sigmoidf_acc(th2[tid * 4 + 3]) - 1.0f;
        float a0 = u0 + 1.0f, a1 = u1;
        float b0 = 0.5f * u2, b1 = 0.5f * u3;
        float dy = fmaxf(fmaf(v, a0, b0), fmaf(v, a1, b1));
        float sg = sigmoidf_acc(dy);
        outArr[b * 256 + c] = (int)fminf(ceilf(64.0f * sg), clampv);
    }
}

// ---------------------------------------------------------------------------
// Kernel 3: out = x * scale * !inside. PDL consumer: blocks launch during the
// mlp window, front-issue their 8 streaming x-loads (independent of mlp
// results), wait for mlp completion, then mask + stream stores.
// ---------------------------------------------------------------------------
__global__ void __launch_bounds__(512) k_apply(const float* __restrict__ x,
                                               float* __restrict__ out) {
    const int sub = threadIdx.x >> 7;        // 0..3: which plane in this block
    const int t   = threadIdx.x & 127;       // 0..127 within plane
    const int plane = blockIdx.x * 4 + sub;

    const float4* xp = reinterpret_cast<const float4*>(x) + (size_t)plane * (HW / 4);
    float4* op = reinterpret_cast<float4*>(out) + (size_t)plane * (HW / 4);

    float4 v[8];
#pragma unroll
    for (int i = 0; i < 8; i++) v[i] = __ldcs(xp + t + i * 128);

    GRID_DEP_WAIT();   // g_scale/g_sx/g_sy now visible

    const float sc = g_scale[plane];
    const int sx = g_sx[plane];
    const int sy = g_sy[plane];

#pragma unroll
    for (int i = 0; i < 8; i++) {
        int p = t + i * 128;        // float4 index within plane
        int row = p >> 4;           // (p*4) / 64
        int col = (p & 15) * 4;     // (p*4) % 64
        v[i].x *= sc; v[i].y *= sc; v[i].z *= sc; v[i].w *= sc;
        if (row >= sx && row < sx + RH) {
            if (col + 0 >= sy && col + 0 < sy + RW) v[i].x = 0.f;
            if (col + 1 >= sy && col + 1 < sy + RW) v[i].y = 0.f;
            if (col + 2 >= sy && col + 2 < sy + RW) v[i].z = 0.f;
            if (col + 3 >= sy && col + 3 < sy + RW) v[i].w = 0.f;
        }
        __stcs(op + p, v[i]);
    }
}

// ---------------------------------------------------------------------------
extern "C" void kernel_launch(void* const* d_in, const int* in_sizes, int n_in,
                              void* d_out, int out_size) {
    const float* x       = (const float*)d_in[0];
    const float* se_w1   = (const float*)d_in[1];
    const float* se_w2   = (const float*)d_in[2];
    const float* ch_w    = (const float*)d_in[3];
    const float* ch_b    = (const float*)d_in[4];
    const float* cw_w    = (const float*)d_in[5];
    const float* cw_b    = (const float*)d_in[6];
    const float* dh_fc1w = (const float*)d_in[7];
    const float* dh_fc1b = (const float*)d_in[8];
    const float* dh_fc2w = (const float*)d_in[9];
    const float* dh_fc2b = (const float*)d_in[10];
    const float* dw_fc1w = (const float*)d_in[11];
    const float* dw_fc1b = (const float*)d_in[12];
    const float* dw_fc2w = (const float*)d_in[13];
    const float* dw_fc2b = (const float*)d_in[14];
    float* out = (float*)d_out;

    // k_mean: normal launch (signals dependents internally, late)
    k_mean<<<PLANES, 256>>>(x);

    // k_mlp: PDL — launches during k_mean's drain; waits internally
    {
        cudaLaunchConfig_t cfg = {};
        cfg.gridDim  = dim3(B, 2, QUARTERS);
        cfg.blockDim = dim3(512, 1, 1);
        cfg.stream   = 0;
        cudaLaunchAttribute attr[1];
        attr[0].id = cudaLaunchAttributeProgrammaticStreamSerialization;
        attr[0].val.programmaticStreamSerializationAllowed = 1;
        cfg.attrs = attr;
        cfg.numAttrs = 1;
        cudaLaunchKernelEx(&cfg, k_mlp,
                           se_w1, se_w2, ch_w, ch_b, cw_w, cw_b,
                           dh_fc1w, dh_fc1b, dh_fc2w, dh_fc2b,
                           dw_fc1w, dw_fc1b, dw_fc2w, dw_fc2b);
    }

    // k_apply: PDL — launches during the mlp window, front-loads x, waits.
    {
        cudaLaunchConfig_t cfg = {};
        cfg.gridDim  = dim3(PLANES / 4, 1, 1);
        cfg.blockDim = dim3(512, 1, 1);
        cfg.stream   = 0;
        cudaLaunchAttribute attr[1];
        attr[0].id = cudaLaunchAttributeProgrammaticStreamSerialization;
        attr[0].val.programmaticStreamSerializationAllowed = 1;
        cfg.attrs = attr;
        cfg.numAttrs = 1;
        cudaLaunchKernelEx(&cfg, k_apply, x, out);
    }
}

// round 14
// speedup vs baseline: 1.0221x; 1.0221x over previous
#include <cuda_runtime.h>
#include <math.h>

// Shapes (fixed by the problem)
#define B 32
#define C 256
#define H 64
#define W 64
#define HW (H*W)            // 4096
#define PLANES (B*C)        // 8192
#define RH 3                // int(0.05*64)
#define RW 6                // int(0.1*64)
#define CLAMP_SX 61.0f      // h - rh
#define CLAMP_SY 58.0f      // w - rw

#define QUARTERS 4          // fc2/final split factor for k_mlp

// Scratch (no cudaMalloc allowed)
__device__ float g_mean[PLANES];
__device__ float g_scale[PLANES];
__device__ int   g_sx[PLANES];
__device__ int   g_sy[PLANES];

// ---------------------------------------------------------------------------
// Kernel 1: per-(b,c) mean. Same geometry as the efficient k_apply:
// 512 threads, 4 planes per block, 8 front-batched streaming float4 loads
// per thread (MLP_p1=8). 2048 blocks.
// ---------------------------------------------------------------------------
__global__ void __launch_bounds__(512) k_mean(const float* __restrict__ x) {
    const int sub = threadIdx.x >> 7;        // 0..3: plane within block
    const int t   = threadIdx.x & 127;       // 0..127 within plane
    const int wid  = threadIdx.x >> 5;       // 0..15
    const int lane = threadIdx.x & 31;
    const int plane = blockIdx.x * 4 + sub;

    const float4* xp = reinterpret_cast<const float4*>(x) + (size_t)plane * (HW / 4);

    float4 v[8];
#pragma unroll
    for (int i = 0; i < 8; i++) v[i] = __ldcs(xp + t + i * 128);

    float s = 0.f;
#pragma unroll
    for (int i = 0; i < 8; i++) s += (v[i].x + v[i].y) + (v[i].z + v[i].w);

#pragma unroll
    for (int o = 16; o; o >>= 1) s += __shfl_xor_sync(0xffffffffu, s, o);

    __shared__ float ws[16];                 // 4 warps per plane x 4 planes
    if (lane == 0) ws[wid] = s;
    __syncthreads();
    if (t == 0) {
        float tot = ws[sub * 4] + ws[sub * 4 + 1] + ws[sub * 4 + 2] + ws[sub * 4 + 3];
        g_mean[plane] = tot * (1.0f / (float)HW);
    }
}

// ---------------------------------------------------------------------------
// Kernel 2: MLP math. grid = (B, 2, QUARTERS) — proven R10 configuration.
// Each block computes SE + vh + th1 redundantly, and only its quarter of
// fc2 + final channels.
// ---------------------------------------------------------------------------
__device__ __forceinline__ float sigmoidf_acc(float v) {
    return 1.0f / (1.0f + expf(-v));
}

__device__ __forceinline__ float warp_red(float s) {
#pragma unroll
    for (int o = 16; o; o >>= 1) s += __shfl_xor_sync(0xffffffffu, s, o);
    return s;
}

__global__ void __launch_bounds__(512) k_mlp(
    const float* __restrict__ se_w1,   // (16,256)
    const float* __restrict__ se_w2,   // (256,16)
    const float* __restrict__ ch_w, const float* __restrict__ ch_b,
    const float* __restrict__ cw_w, const float* __restrict__ cw_b,
    const float* __restrict__ dh_fc1w, const float* __restrict__ dh_fc1b,
    const float* __restrict__ dh_fc2w, const float* __restrict__ dh_fc2b,
    const float* __restrict__ dw_fc1w, const float* __restrict__ dw_fc1b,
    const float* __restrict__ dw_fc2w, const float* __restrict__ dw_fc2b)
{
    __shared__ float y[256];
    __shared__ float t1[16];
    __shared__ float gv[256];
    __shared__ float vh[256];
    __shared__ float th1[64];
    __shared__ float th2[256];    // this block's quarter of fc2 outputs

    int b    = blockIdx.x;
    int br   = blockIdx.y;
    int q    = blockIdx.z;        // fc2 quarter 0..3
    int tid  = threadIdx.x;
    int wid  = tid >> 5;          // 0..15
    int lane = tid & 31;

    const float* cw   = br ? cw_w    : ch_w;
    const float* cb   = br ? cw_b    : ch_b;
    const float* fc1w = br ? dw_fc1w : dh_fc1w;
    const float* fc1b = br ? dw_fc1b : dh_fc1b;
    const float* fc2w = br ? dw_fc2w : dh_fc2w;
    const float* fc2b = br ? dw_fc2b : dh_fc2b;
    int* outArr = br ? g_sy : g_sx;
    float clampv = br ? CLAMP_SY : CLAMP_SX;

    if (tid < 256) y[tid] = g_mean[b * 256 + tid];
    __syncthreads();

    float yreg[8];
#pragma unroll
    for (int k = 0; k < 8; k++) yreg[k] = y[lane + k * 32];

    // SE squeeze: 1 output per warp
    {
        const float* r = se_w1 + wid * 256;
        float s = 0.f;
#pragma unroll
        for (int k = 0; k < 8; k++) s = fmaf(yreg[k], r[lane + k * 32], s);
        s = warp_red(s);
        if (lane == 0) t1[wid] = fmaxf(s, 0.f);
    }
    __syncthreads();

    // SE excite
    if (tid < 256) {
        const float4* r = reinterpret_cast<const float4*>(se_w2 + tid * 16);
        const float4* t = reinterpret_cast<const float4*>(t1);
        float s = 0.f;
#pragma unroll
        for (int j = 0; j < 4; j++) {
            float4 wv = r[j];
            float4 tv = t[j];
            s = fmaf(wv.x, tv.x, fmaf(wv.y, tv.y, fmaf(wv.z, tv.z, fmaf(wv.w, tv.w, s))));
        }
        float sg = sigmoidf_acc(s);
        if (br == 0 && q == 0) g_scale[b * 256 + tid] = sg;
        gv[tid] = y[tid] * sg;
    }
    __syncthreads();

    float greg[8];
#pragma unroll
    for (int k = 0; k < 8; k++) greg[k] = gv[lane + k * 32];

    // vh[256] = gv @ cw^T + cb : 16 outputs per warp
#pragma unroll 8
    for (int i = 0; i < 16; i++) {
        int o = wid * 16 + i;
        const float* r = cw + o * 256;
        float s = 0.f;
#pragma unroll
        for (int k = 0; k < 8; k++) s = fmaf(greg[k], r[lane + k * 32], s);
        s = warp_red(s);
        if (lane == 0) vh[o] = s + cb[o];
    }
    __syncthreads();

    float vreg[8];
#pragma unroll
    for (int k = 0; k < 8; k++) vreg[k] = vh[lane + k * 32];

    // th1[64] = relu(vh @ fc1w^T + fc1b) : 4 outputs per warp
#pragma unroll
    for (int i = 0; i < 4; i++) {
        int o = wid * 4 + i;
        const float* r = fc1w + o * 256;
        float s = 0.f;
#pragma unroll
        for (int k = 0; k < 8; k++) s = fmaf(vreg[k], r[lane + k * 32], s);
        s = warp_red(s);
        if (lane == 0) th1[o] = fmaxf(s + fc1b[o], 0.f);
    }
    __syncthreads();

    float t1a = th1[lane * 2];
    float t1b = th1[lane * 2 + 1];

    // th2 quarter: outputs m in [q*256, q*256+256), 16 per warp
#pragma unroll 8
    for (int i = 0; i < 16; i++) {
        int m = q * 256 + wid * 16 + i;
        float2 wv = reinterpret_cast<const float2*>(fc2w + m * 64)[lane];
        float s = fmaf(t1a, wv.x, t1b * wv.y);
        s = warp_red(s);
        if (lane == 0) th2[wid * 16 + i] = s + fc2b[m];
    }
    __syncthreads();

    // dyrelu + sigmoid + ceil/clamp for this quarter's 64 channels
    if (tid < 64) {
        int c = q * 64 + tid;            // global channel
        float v = vh[c];
        float u0 = 2.0f * sigmoidf_acc(th2[tid * 4 + 0]) - 1.0f;
        float u1 = 2.0f * sigmoidf_acc(th2[tid * 4 + 1]) - 1.0f;
        float u2 = 2.0f * sigmoidf_acc(th2[tid * 4 + 2]) - 1.0f;
        float u3 = 2.0f * sigmoidf_acc(th2[tid * 4 + 3]) - 1.0f;
        float a0 = u0 + 1.0f, a1 = u1;
        float b0 = 0.5f * u2, b1 = 0.5f * u3;
        float dy = fmaxf(fmaf(v, a0, b0), fmaf(v, a1, b1));
        float sg = sigmoidf_acc(dy);
        outArr[b * 256 + c] = (int)fminf(ceilf(64.0f * sg), clampv);
    }
}

// ---------------------------------------------------------------------------
// Kernel 3: out = x * scale * !inside. Proven R8/R10 version (36.2us / 74%).
// 512 threads, 4 planes per block; 8 front-batched streaming float4 loads,
// then mask + streaming stores.
// ---------------------------------------------------------------------------
__global__ void __launch_bounds__(512) k_apply(const float* __restrict__ x,
                                               float* __restrict__ out) {
    const int sub = threadIdx.x >> 7;        // 0..3: which plane in this block
    const int t   = threadIdx.x & 127;       // 0..127 within plane
    const int plane = blockIdx.x * 4 + sub;

    const float sc = g_scale[plane];
    const int sx = g_sx[plane];
    const int sy = g_sy[plane];

    const float4* xp = reinterpret_cast<const float4*>(x) + (size_t)plane * (HW / 4);
    float4* op = reinterpret_cast<float4*>(out) + (size_t)plane * (HW / 4);

    float4 v[8];
#pragma unroll
    for (int i = 0; i < 8; i++) v[i] = __ldcs(xp + t + i * 128);

#pragma unroll
    for (int i = 0; i < 8; i++) {
        int p = t + i * 128;        // float4 index within plane
        int row = p >> 4;           // (p*4) / 64
        int col = (p & 15) * 4;     // (p*4) % 64
        v[i].x *= sc; v[i].y *= sc; v[i].z *= sc; v[i].w *= sc;
        if (row >= sx && row < sx + RH) {
            if (col + 0 >= sy && col + 0 < sy + RW) v[i].x = 0.f;
            if (col + 1 >= sy && col + 1 < sy + RW) v[i].y = 0.f;
            if (col + 2 >= sy && col + 2 < sy + RW) v[i].z = 0.f;
            if (col + 3 >= sy && col + 3 < sy + RW) v[i].w = 0.f;
        }
        __stcs(op + p, v[i]);
    }
}

// ---------------------------------------------------------------------------
extern "C" void kernel_launch(void* const* d_in, const int* in_sizes, int n_in,
                              void* d_out, int out_size) {
    const float* x       = (const float*)d_in[0];
    const float* se_w1   = (const float*)d_in[1];
    const float* se_w2   = (const float*)d_in[2];
    const float* ch_w    = (const float*)d_in[3];
    const float* ch_b    = (const float*)d_in[4];
    const float* cw_w    = (const float*)d_in[5];
    const float* cw_b    = (const float*)d_in[6];
    const float* dh_fc1w = (const float*)d_in[7];
    const float* dh_fc1b = (const float*)d_in[8];
    const float* dh_fc2w = (const float*)d_in[9];
    const float* dh_fc2b = (const float*)d_in[10];
    const float* dw_fc1w = (const float*)d_in[11];
    const float* dw_fc1b = (const float*)d_in[12];
    const float* dw_fc2w = (const float*)d_in[13];
    const float* dw_fc2b = (const float*)d_in[14];
    float* out = (float*)d_out;

    k_mean<<<PLANES / 4, 512>>>(x);
    dim3 mg(B, 2, QUARTERS);
    k_mlp<<<mg, 512>>>(se_w1, se_w2, ch_w, ch_b, cw_w, cw_b,
                       dh_fc1w, dh_fc1b, dh_fc2w, dh_fc2b,
                       dw_fc1w, dw_fc1b, dw_fc2w, dw_fc2b);
    k_apply<<<PLANES / 4, 512>>>(x, out);
}